// round 15
// baseline (speedup 1.0000x reference)
#include <cuda_runtime.h>
#include <math.h>

#define D_MODEL 1024
#define NUM_HEADS 16
#define DEPTH 64
#define BATCH 4
#define SEQLEN 2048
#define M_TOTAL 8192
#define LOG2E 1.4426950408889634f

// ---------------- scratch (tf32 bit patterns, permuted layouts) ----------------
__device__ unsigned g_Aq[M_TOTAL * D_MODEL];
__device__ unsigned g_Av[M_TOTAL * D_MODEL];
__device__ unsigned g_Wq[D_MODEL * D_MODEL];
__device__ unsigned g_Wk[D_MODEL * D_MODEL];
__device__ unsigned g_Wv[D_MODEL * D_MODEL];
__device__ unsigned g_Wo[D_MODEL * D_MODEL];
__device__ unsigned g_Q[BATCH * NUM_HEADS * SEQLEN * DEPTH];
__device__ unsigned g_K[BATCH * NUM_HEADS * SEQLEN * DEPTH];
__device__ unsigned g_V[BATCH * NUM_HEADS * SEQLEN * DEPTH];
__device__ unsigned g_ctx[M_TOTAL * D_MODEL];

// ---------------- helpers ----------------
__device__ __forceinline__ unsigned f2tf(float f) {
    unsigned u; asm("cvt.rna.tf32.f32 %0, %1;" : "=r"(u) : "f"(f)); return u;
}
__device__ __forceinline__ float ex2(float x) {
    float r; asm("ex2.approx.ftz.f32 %0, %1;" : "=f"(r) : "f"(x)); return r;
}
__device__ __host__ __forceinline__ int gmap(int k) {
    int kk = k & 31, ks = kk >> 3;
    return (k & ~31) + ((ks >> 1) << 4) + ((kk & 3) << 2) + ((ks & 1) << 1) + ((kk >> 2) & 1);
}
__device__ __forceinline__ int qkmap(int d) {
    int ks = d >> 3;
    return ((ks >> 1) << 4) + ((d & 3) << 2) + ((ks & 1) << 1) + ((d >> 2) & 1);
}
__device__ __forceinline__ int wvmap(int c) {
    int ks = c >> 3;
    return ((ks >> 1) << 4) + (((c >> 1) & 3) << 2) + ((ks & 1) << 1) + (c & 1);
}
__device__ __forceinline__ unsigned smem_u32(const void* p) {
    return (unsigned)__cvta_generic_to_shared(p);
}
#define CP16(d, s) asm volatile("cp.async.cg.shared.global [%0], [%1], 16;\n" :: "r"(d), "l"(s))
#define CP_COMMIT() asm volatile("cp.async.commit_group;\n")
#define CP_WAIT(n)  asm volatile("cp.async.wait_group %0;\n" :: "n"(n))

__device__ __forceinline__ void mma8(float* c, const unsigned* a, const unsigned* b) {
    asm volatile(
        "mma.sync.aligned.m16n8k8.row.col.f32.tf32.tf32.f32 "
        "{%0,%1,%2,%3},{%4,%5,%6,%7},{%8,%9},{%0,%1,%2,%3};\n"
        : "+f"(c[0]), "+f"(c[1]), "+f"(c[2]), "+f"(c[3])
        : "r"(a[0]), "r"(a[1]), "r"(a[2]), "r"(a[3]), "r"(b[0]), "r"(b[1]));
}

// ---------------- pre-convert (merged): inputs (query+value) ----------------
__global__ __launch_bounds__(256)
void cvt_inputs(const float* __restrict__ q, const float* __restrict__ v,
                unsigned* __restrict__ dq, unsigned* __restrict__ dv)
{
    int i = blockIdx.x * 256 + threadIdx.x;          // [0, 2*nA)
    const int nA = M_TOTAL * D_MODEL;
    const float* src; unsigned* dst;
    if (i < nA) { src = q; dst = dq; }
    else        { src = v; dst = dv; i -= nA; }
    int k = i & 1023;
    dst[(i & ~1023) + gmap(k)] = f2tf(src[i]);
}

// ---------------- pre-convert (merged): 4 weight matrices ----------------
__global__ __launch_bounds__(256)
void cvt_weights(const float* __restrict__ wq, const float* __restrict__ wk,
                 const float* __restrict__ wv, const float* __restrict__ wo,
                 unsigned* __restrict__ dq, unsigned* __restrict__ dk,
                 unsigned* __restrict__ dv, unsigned* __restrict__ dwo,
                 float qscale)
{
    int i = blockIdx.x * 256 + threadIdx.x;          // [0, 4*nW), nW = 2^20
    const int seg = i >> 20;
    const int j = i & ((1 << 20) - 1);
    const float* src = seg == 0 ? wq : seg == 1 ? wk : seg == 2 ? wv : wo;
    unsigned* dst    = seg == 0 ? dq : seg == 1 ? dk : seg == 2 ? dv : dwo;
    const float scale = seg == 0 ? qscale : 1.0f;
    int k = j & 1023;
    dst[(j & ~1023) + gmap(k)] = f2tf(src[j] * scale);
}

// ---------------- tf32 GEMM, 3-stage cp.async pipeline, LDS.128 frags ----------------
#define GEMM_SMEM (24576 * 4)   // 3 stages x (A 128x32 + B 128x32) = 96KB

__global__ __launch_bounds__(256, 2)
void gemm_tf32(const unsigned* __restrict__ A, const unsigned* __restrict__ W,
               const float* __restrict__ bias, float bscale, void* Cv, int mode)
{
    extern __shared__ unsigned smw[];
    const int tid  = threadIdx.x;
    const int lane = tid & 31;
    const int warp = tid >> 5;
    const int g = lane >> 2, t = lane & 3;
    const int wm = warp & 1;
    const int wn = warp >> 1;
    const long rowA0 = (long)blockIdx.y * 128;
    const long colB0 = (long)blockIdx.x * 128;
    const int swz = (g & 1) << 4;

    float acc[4][4][4];
#pragma unroll
    for (int mi = 0; mi < 4; mi++)
#pragma unroll
        for (int ni = 0; ni < 4; ni++)
#pragma unroll
            for (int r = 0; r < 4; r++) acc[mi][ni][r] = 0.f;

    auto issue = [&](int stage, int k0) {
        unsigned* Ab = smw + stage * 8192;
        unsigned* Bb = Ab + 4096;
#pragma unroll
        for (int i = 0; i < 4; i++) {
            const int idx = tid + i * 256;
            const int r = idx >> 3, cp = idx & 7;
            const int w = r * 32 + ((cp * 4) ^ ((r & 1) << 4));
            CP16(smem_u32(Ab + w), A + (rowA0 + r) * 1024 + k0 + cp * 4);
            CP16(smem_u32(Bb + w), W + (colB0 + r) * 1024 + k0 + cp * 4);
        }
        CP_COMMIT();
    };

    issue(0, 0);
    issue(1, 32);
    int st = 0, st2 = 2;    // compute stage, refill stage
    for (int c = 0; c < 32; c++) {
        if (c < 31) CP_WAIT(1); else CP_WAIT(0);
        __syncthreads();
        if (c < 30) {
            issue(st2, (c + 2) * 32);
            if (++st2 == 3) st2 = 0;
        }

        const unsigned* Aw = smw + st * 8192;
        const unsigned* Bw = Aw + 4096;
        if (++st == 3) st = 0;
#pragma unroll
        for (int m = 0; m < 2; m++) {
            const int co = (m * 16 + t * 4) ^ swz;
            unsigned afA[4][4], afB[4][4], bfA[4][2], bfB[4][2];
#pragma unroll
            for (int mi = 0; mi < 4; mi++) {
                const int r = wm * 64 + mi * 16 + g;
                uint4 u = *(const uint4*)(Aw + r * 32 + co);
                uint4 v = *(const uint4*)(Aw + (r + 8) * 32 + co);
                afA[mi][0] = u.x; afA[mi][1] = v.x; afA[mi][2] = u.y; afA[mi][3] = v.y;
                afB[mi][0] = u.z; afB[mi][1] = v.z; afB[mi][2] = u.w; afB[mi][3] = v.w;
            }
#pragma unroll
            for (int ni = 0; ni < 4; ni++) {
                const int cc = wn * 32 + ni * 8 + g;
                uint4 w2 = *(const uint4*)(Bw + cc * 32 + co);
                bfA[ni][0] = w2.x; bfA[ni][1] = w2.y;
                bfB[ni][0] = w2.z; bfB[ni][1] = w2.w;
            }
#pragma unroll
            for (int mi = 0; mi < 4; mi++)
#pragma unroll
                for (int ni = 0; ni < 4; ni++) {
                    mma8(acc[mi][ni], afA[mi], bfA[ni]);
                    mma8(acc[mi][ni], afB[mi], bfB[ni]);
                }
        }
    }

    float* Cf = (float*)Cv;
    unsigned* Cu = (unsigned*)Cv;
#pragma unroll
    for (int mi = 0; mi < 4; mi++) {
#pragma unroll
        for (int ni = 0; ni < 4; ni++) {
            const int row = (int)rowA0 + wm * 64 + mi * 16 + g;
            const int col = (int)colB0 + wn * 32 + ni * 8 + 2 * t;
            const float b0 = bias[col] * bscale, b1 = bias[col + 1] * bscale;
            const float v00 = acc[mi][ni][0] + b0, v01 = acc[mi][ni][1] + b1;
            const float v10 = acc[mi][ni][2] + b0, v11 = acc[mi][ni][3] + b1;
            if (mode == 0) {
                *(float2*)&Cf[(long)row * 1024 + col] = make_float2(v00, v01);
                *(float2*)&Cf[(long)(row + 8) * 1024 + col] = make_float2(v10, v11);
            } else if (mode == 1 || mode == 3) {
                const int h = col >> 6, d = col & 63;
                const int d0 = qkmap(d), d1 = qkmap(d + 1);
#pragma unroll
                for (int half = 0; half < 2; half++) {
                    const int r2 = row + half * 8;
                    const int b_ = r2 >> 11;
                    int l = r2 & 2047;
                    if (mode == 3) l = (l & ~7) | (((l & 3) << 1) | ((l & 7) >> 2));
                    long base = ((long)(b_ * 16 + h) * 2048 + l) * 64;
                    Cu[base + d0] = f2tf(half ? v10 : v00);
                    Cu[base + d1] = f2tf(half ? v11 : v01);
                }
            } else {
                const int h = col >> 6, d = col & 63;
#pragma unroll
                for (int half = 0; half < 2; half++) {
                    const int r2 = row + half * 8;
                    const int b_ = r2 >> 11, l = r2 & 2047;
                    const int kt = l >> 6, rr = l & 63;
                    const int cst = (rr & ~7) | (((rr & 3) << 1) | ((rr & 7) >> 2));
                    long base = (long)(b_ * 16 + h) * 131072 + kt * 4096 + wvmap(cst);
                    Cu[base + d * 64]       = f2tf(half ? v10 : v00);
                    Cu[base + (d + 1) * 64] = f2tf(half ? v11 : v01);
                }
            }
        }
    }
}

// ---------------- tf32 flash attention (R7 structure, passing) ----------------
#define ATT_SMEM (24576 * 4)   // 98304B

__global__ __launch_bounds__(256, 2)
void attn_tf32(const unsigned* __restrict__ Q, const unsigned* __restrict__ K,
               const unsigned* __restrict__ V, unsigned* __restrict__ ctx)
{
    extern __shared__ unsigned smw[];
    unsigned* Kb0 = smw;
    unsigned* Kb1 = smw + 4096;
    unsigned* Vb0 = smw + 8192;
    unsigned* Vb1 = smw + 12288;
    unsigned* Qs  = smw + 16384;

    const int tid  = threadIdx.x;
    const int lane = tid & 31;
    const int warp = tid >> 5;
    const int g = lane >> 2, t = lane & 3;
    const int qt = blockIdx.x, h = blockIdx.y, b = blockIdx.z;
    const long base = (long)(b * 16 + h) * 131072;
    const int qr = warp * 16;
    const int swz = (g & 1) << 4;

    auto issueKV = [&](unsigned* Kd, unsigned* Vd, int kt) {
        const unsigned* ksrc = K + base + kt * 4096;
        const unsigned* vsrc = V + base + kt * 4096;
#pragma unroll
        for (int i = 0; i < 4; i++) {
            const int idx = tid + i * 256;
            const int r = idx >> 4, cp = idx & 15;
            const int w = r * 64 + ((cp * 4) ^ ((r & 1) << 4));
            CP16(smem_u32(Kd + w), ksrc + r * 64 + cp * 4);
            CP16(smem_u32(Vd + w), vsrc + r * 64 + cp * 4);
        }
        CP_COMMIT();
    };

    {
        const unsigned* qsrc = Q + base + (long)qt * 8192;
#pragma unroll
        for (int i = 0; i < 8; i++) {
            const int idx = tid + i * 256;
            const int r = idx >> 4, cp = idx & 15;
            CP16(smem_u32(Qs + r * 64 + ((cp * 4) ^ ((r & 1) << 4))), qsrc + r * 64 + cp * 4);
        }
        CP_COMMIT();
    }
    issueKV(Kb0, Vb0, 0);
    CP_WAIT(1);
    __syncthreads();

    unsigned qf[8][4];
#pragma unroll
    for (int m = 0; m < 4; m++) {
        const int co = (m * 16 + t * 4) ^ swz;
        uint4 u = *(const uint4*)(Qs + (qr + g) * 64 + co);
        uint4 v = *(const uint4*)(Qs + (qr + g + 8) * 64 + co);
        qf[2 * m][0]     = u.x; qf[2 * m][1]     = v.x; qf[2 * m][2]     = u.y; qf[2 * m][3]     = v.y;
        qf[2 * m + 1][0] = u.z; qf[2 * m + 1][1] = v.z; qf[2 * m + 1][2] = u.w; qf[2 * m + 1][3] = v.w;
    }

    float l0 = 0.f, l1 = 0.f;
    float o[8][4];
#pragma unroll
    for (int ni = 0; ni < 8; ni++)
#pragma unroll
        for (int r = 0; r < 4; r++) o[ni][r] = 0.f;

    for (int kt = 0; kt < 32; kt++) {
        CP_WAIT(0);
        __syncthreads();
        if (kt < 31) issueKV((kt & 1) ? Kb0 : Kb1, (kt & 1) ? Vb0 : Vb1, kt + 1);
        const unsigned* Kw = (kt & 1) ? Kb1 : Kb0;
        const unsigned* Vw = (kt & 1) ? Vb1 : Vb0;

        float s[8][4];
#pragma unroll
        for (int ni = 0; ni < 8; ni++) {
#pragma unroll
            for (int r = 0; r < 4; r++) s[ni][r] = 0.f;
            const int rk = (ni * 8 + g) * 64;
#pragma unroll
            for (int m = 0; m < 4; m++) {
                uint4 kb = *(const uint4*)(Kw + rk + ((m * 16 + t * 4) ^ swz));
                unsigned bfA[2] = { kb.x, kb.y };
                unsigned bfB[2] = { kb.z, kb.w };
                mma8(s[ni], qf[2 * m], bfA);
                mma8(s[ni], qf[2 * m + 1], bfB);
            }
        }

#pragma unroll
        for (int ni = 0; ni < 8; ni++) {
            s[ni][0] = __uint_as_float(f2tf(ex2(s[ni][0]))); l0 += s[ni][0];
            s[ni][1] = __uint_as_float(f2tf(ex2(s[ni][1]))); l0 += s[ni][1];
            s[ni][2] = __uint_as_float(f2tf(ex2(s[ni][2]))); l1 += s[ni][2];
            s[ni][3] = __uint_as_float(f2tf(ex2(s[ni][3]))); l1 += s[ni][3];
        }

#pragma unroll
        for (int ni = 0; ni < 8; ni++) {
            const int rd = (ni * 8 + g) * 64;
#pragma unroll
            for (int m = 0; m < 4; m++) {
                uint4 vb = *(const uint4*)(Vw + rd + ((m * 16 + t * 4) ^ swz));
                unsigned pfA[4] = { __float_as_uint(s[2 * m][0]), __float_as_uint(s[2 * m][2]),
                                    __float_as_uint(s[2 * m][1]), __float_as_uint(s[2 * m][3]) };
                unsigned pfB[4] = { __float_as_uint(s[2 * m + 1][0]), __float_as_uint(s[2 * m + 1][2]),
                                    __float_as_uint(s[2 * m + 1][1]), __float_as_uint(s[2 * m + 1][3]) };
                unsigned bfA[2] = { vb.x, vb.y };
                unsigned bfB[2] = { vb.z, vb.w };
                mma8(o[ni], pfA, bfA);
                mma8(o[ni], pfB, bfB);
            }
        }
    }

    l0 += __shfl_xor_sync(0xffffffffu, l0, 1);
    l0 += __shfl_xor_sync(0xffffffffu, l0, 2);
    l1 += __shfl_xor_sync(0xffffffffu, l1, 1);
    l1 += __shfl_xor_sync(0xffffffffu, l1, 2);
    const float inv0 = 1.0f / l0, inv1 = 1.0f / l1;
    const int row0 = qt * 128 + qr + g;
#pragma unroll
    for (int ni = 0; ni < 8; ni++) {
        const int c = h * 64 + ni * 8 + 2 * t;
        const int cm0 = gmap(c), cm1 = gmap(c + 1);
        long p0 = ((long)(b * 2048 + row0)) * 1024;
        long p1 = ((long)(b * 2048 + row0 + 8)) * 1024;
        ctx[p0 + cm0] = f2tf(o[ni][0] * inv0);
        ctx[p0 + cm1] = f2tf(o[ni][1] * inv0);
        ctx[p1 + cm0] = f2tf(o[ni][2] * inv1);
        ctx[p1 + cm1] = f2tf(o[ni][3] * inv1);
    }
}

// ---------------- launch ----------------
extern "C" void kernel_launch(void* const* d_in, const int* in_sizes, int n_in,
                              void* d_out, int out_size)
{
    const float* query = (const float*)d_in[0];
    const float* value = (const float*)d_in[1];
    const float* wq = (const float*)d_in[2];
    const float* bq = (const float*)d_in[3];
    const float* wk = (const float*)d_in[4];
    const float* bk = (const float*)d_in[5];
    const float* wv = (const float*)d_in[6];
    const float* bv = (const float*)d_in[7];
    const float* wo = (const float*)d_in[8];
    const float* bo = (const float*)d_in[9];
    float* out = (float*)d_out;

    unsigned *Aq, *Av, *Wq, *Wk, *Wv, *Wo, *Qp, *Kp, *Vp, *Cp;
    cudaGetSymbolAddress((void**)&Aq, g_Aq);
    cudaGetSymbolAddress((void**)&Av, g_Av);
    cudaGetSymbolAddress((void**)&Wq, g_Wq);
    cudaGetSymbolAddress((void**)&Wk, g_Wk);
    cudaGetSymbolAddress((void**)&Wv, g_Wv);
    cudaGetSymbolAddress((void**)&Wo, g_Wo);
    cudaGetSymbolAddress((void**)&Qp, g_Q);
    cudaGetSymbolAddress((void**)&Kp, g_K);
    cudaGetSymbolAddress((void**)&Vp, g_V);
    cudaGetSymbolAddress((void**)&Cp, g_ctx);

    const float qscale = 0.125f * LOG2E;
    const int nA = M_TOTAL * D_MODEL;
    const int nW = D_MODEL * D_MODEL;

    // launch order chosen so ncu (-s 5 -c 1) captures attn_tf32 (6th launch)
    cvt_inputs<<<2 * nA / 256, 256>>>(query, value, Aq, Av);
    cvt_weights<<<4 * nW / 256, 256>>>(wq, wk, wv, wo, Wq, Wk, Wv, Wo, qscale);

    cudaFuncSetAttribute(gemm_tf32, cudaFuncAttributeMaxDynamicSharedMemorySize, GEMM_SMEM);
    cudaFuncSetAttribute(attn_tf32, cudaFuncAttributeMaxDynamicSharedMemorySize, ATT_SMEM);

    const dim3 gGemm(8, 64);
    gemm_tf32<<<gGemm, 256, GEMM_SMEM>>>(Aq, Wq, bq, qscale, Qp, 1);
    gemm_tf32<<<gGemm, 256, GEMM_SMEM>>>(Av, Wk, bk, 1.0f, Kp, 3);
    gemm_tf32<<<gGemm, 256, GEMM_SMEM>>>(Av, Wv, bv, 1.0f, Vp, 2);

    attn_tf32<<<dim3(16, 16, 4), 256, ATT_SMEM>>>(Qp, Kp, Vp, Cp);

    gemm_tf32<<<gGemm, 256, GEMM_SMEM>>>(Cp, Wo, bo, 1.0f, out, 0);
    (void)in_sizes; (void)n_in; (void)out_size;
}

// round 16
// speedup vs baseline: 1.0471x; 1.0471x over previous
#include <cuda_runtime.h>
#include <math.h>

#define D_MODEL 1024
#define NUM_HEADS 16
#define DEPTH 64
#define BATCH 4
#define SEQLEN 2048
#define M_TOTAL 8192
#define LOG2E 1.4426950408889634f

// ---------------- scratch (tf32 bit patterns, permuted layouts) ----------------
__device__ unsigned g_Aq[M_TOTAL * D_MODEL];
__device__ unsigned g_Av[M_TOTAL * D_MODEL];
__device__ unsigned g_Wq[D_MODEL * D_MODEL];
__device__ unsigned g_Wk[D_MODEL * D_MODEL];
__device__ unsigned g_Wv[D_MODEL * D_MODEL];
__device__ unsigned g_Wo[D_MODEL * D_MODEL];
__device__ unsigned g_Q[BATCH * NUM_HEADS * SEQLEN * DEPTH];
__device__ unsigned g_K[BATCH * NUM_HEADS * SEQLEN * DEPTH];
__device__ unsigned g_V[BATCH * NUM_HEADS * SEQLEN * DEPTH];
__device__ unsigned g_ctx[M_TOTAL * D_MODEL];

// ---------------- helpers ----------------
__device__ __forceinline__ unsigned f2tf(float f) {
    unsigned u; asm("cvt.rna.tf32.f32 %0, %1;" : "=r"(u) : "f"(f)); return u;
}
__device__ __forceinline__ float ex2(float x) {
    float r; asm("ex2.approx.ftz.f32 %0, %1;" : "=f"(r) : "f"(x)); return r;
}
__device__ __host__ __forceinline__ int gmap(int k) {
    int kk = k & 31, ks = kk >> 3;
    return (k & ~31) + ((ks >> 1) << 4) + ((kk & 3) << 2) + ((ks & 1) << 1) + ((kk >> 2) & 1);
}
__device__ __forceinline__ int qkmap(int d) {
    int ks = d >> 3;
    return ((ks >> 1) << 4) + ((d & 3) << 2) + ((ks & 1) << 1) + ((d >> 2) & 1);
}
__device__ __forceinline__ int wvmap(int c) {
    int ks = c >> 3;
    return ((ks >> 1) << 4) + (((c >> 1) & 3) << 2) + ((ks & 1) << 1) + (c & 1);
}
__device__ __forceinline__ unsigned smem_u32(const void* p) {
    return (unsigned)__cvta_generic_to_shared(p);
}
#define CP16(d, s) asm volatile("cp.async.cg.shared.global [%0], [%1], 16;\n" :: "r"(d), "l"(s))
#define CP_COMMIT() asm volatile("cp.async.commit_group;\n")
#define CP_WAIT(n)  asm volatile("cp.async.wait_group %0;\n" :: "n"(n))

__device__ __forceinline__ void mma8(float* c, const unsigned* a, const unsigned* b) {
    asm volatile(
        "mma.sync.aligned.m16n8k8.row.col.f32.tf32.tf32.f32 "
        "{%0,%1,%2,%3},{%4,%5,%6,%7},{%8,%9},{%0,%1,%2,%3};\n"
        : "+f"(c[0]), "+f"(c[1]), "+f"(c[2]), "+f"(c[3])
        : "r"(a[0]), "r"(a[1]), "r"(a[2]), "r"(a[3]), "r"(b[0]), "r"(b[1]));
}

// ---------------- pre-convert (merged): inputs ----------------
__global__ __launch_bounds__(256)
void cvt_inputs(const float* __restrict__ q, const float* __restrict__ v,
                unsigned* __restrict__ dq, unsigned* __restrict__ dv)
{
    int i = blockIdx.x * 256 + threadIdx.x;
    const int nA = M_TOTAL * D_MODEL;
    const float* src; unsigned* dst;
    if (i < nA) { src = q; dst = dq; }
    else        { src = v; dst = dv; i -= nA; }
    int k = i & 1023;
    dst[(i & ~1023) + gmap(k)] = f2tf(src[i]);
}

// ---------------- pre-convert (merged): weights ----------------
__global__ __launch_bounds__(256)
void cvt_weights(const float* __restrict__ wq, const float* __restrict__ wk,
                 const float* __restrict__ wv, const float* __restrict__ wo,
                 unsigned* __restrict__ dq, unsigned* __restrict__ dk,
                 unsigned* __restrict__ dv, unsigned* __restrict__ dwo,
                 float qscale)
{
    int i = blockIdx.x * 256 + threadIdx.x;
    const int seg = i >> 20;
    const int j = i & ((1 << 20) - 1);
    const float* src = seg == 0 ? wq : seg == 1 ? wk : seg == 2 ? wv : wo;
    unsigned* dst    = seg == 0 ? dq : seg == 1 ? dk : seg == 2 ? dv : dwo;
    const float scale = seg == 0 ? qscale : 1.0f;
    int k = j & 1023;
    dst[(j & ~1023) + gmap(k)] = f2tf(src[j] * scale);
}

// ---------------- shared GEMM body (3-stage cp.async, LDS.128 frags) ----------------
#define GEMM_SMEM (24576 * 4)   // 3 stages x (A 128x32 + B 128x32) = 96KB

__device__ __forceinline__
void gemm_body(const unsigned* __restrict__ A, const unsigned* __restrict__ W,
               const float* __restrict__ bias, float bscale, void* Cv, int mode,
               int tileX, int tileY, unsigned* smw)
{
    const int tid  = threadIdx.x;
    const int lane = tid & 31;
    const int warp = tid >> 5;
    const int g = lane >> 2, t = lane & 3;
    const int wm = warp & 1;
    const int wn = warp >> 1;
    const long rowA0 = (long)tileY * 128;
    const long colB0 = (long)tileX * 128;
    const int swz = (g & 1) << 4;

    float acc[4][4][4];
#pragma unroll
    for (int mi = 0; mi < 4; mi++)
#pragma unroll
        for (int ni = 0; ni < 4; ni++)
#pragma unroll
            for (int r = 0; r < 4; r++) acc[mi][ni][r] = 0.f;

    auto issue = [&](int stage, int k0) {
        unsigned* Ab = smw + stage * 8192;
        unsigned* Bb = Ab + 4096;
#pragma unroll
        for (int i = 0; i < 4; i++) {
            const int idx = tid + i * 256;
            const int r = idx >> 3, cp = idx & 7;
            const int w = r * 32 + ((cp * 4) ^ ((r & 1) << 4));
            CP16(smem_u32(Ab + w), A + (rowA0 + r) * 1024 + k0 + cp * 4);
            CP16(smem_u32(Bb + w), W + (colB0 + r) * 1024 + k0 + cp * 4);
        }
        CP_COMMIT();
    };

    issue(0, 0);
    issue(1, 32);
    int st = 0, st2 = 2;
    for (int c = 0; c < 32; c++) {
        if (c < 31) CP_WAIT(1); else CP_WAIT(0);
        __syncthreads();
        if (c < 30) {
            issue(st2, (c + 2) * 32);
            if (++st2 == 3) st2 = 0;
        }

        const unsigned* Aw = smw + st * 8192;
        const unsigned* Bw = Aw + 4096;
        if (++st == 3) st = 0;
#pragma unroll
        for (int m = 0; m < 2; m++) {
            const int co = (m * 16 + t * 4) ^ swz;
            unsigned afA[4][4], afB[4][4], bfA[4][2], bfB[4][2];
#pragma unroll
            for (int mi = 0; mi < 4; mi++) {
                const int r = wm * 64 + mi * 16 + g;
                uint4 u = *(const uint4*)(Aw + r * 32 + co);
                uint4 v = *(const uint4*)(Aw + (r + 8) * 32 + co);
                afA[mi][0] = u.x; afA[mi][1] = v.x; afA[mi][2] = u.y; afA[mi][3] = v.y;
                afB[mi][0] = u.z; afB[mi][1] = v.z; afB[mi][2] = u.w; afB[mi][3] = v.w;
            }
#pragma unroll
            for (int ni = 0; ni < 4; ni++) {
                const int cc = wn * 32 + ni * 8 + g;
                uint4 w2 = *(const uint4*)(Bw + cc * 32 + co);
                bfA[ni][0] = w2.x; bfA[ni][1] = w2.y;
                bfB[ni][0] = w2.z; bfB[ni][1] = w2.w;
            }
#pragma unroll
            for (int mi = 0; mi < 4; mi++)
#pragma unroll
                for (int ni = 0; ni < 4; ni++) {
                    mma8(acc[mi][ni], afA[mi], bfA[ni]);
                    mma8(acc[mi][ni], afB[mi], bfB[ni]);
                }
        }
    }

    float* Cf = (float*)Cv;
    unsigned* Cu = (unsigned*)Cv;
#pragma unroll
    for (int mi = 0; mi < 4; mi++) {
#pragma unroll
        for (int ni = 0; ni < 4; ni++) {
            const int row = (int)rowA0 + wm * 64 + mi * 16 + g;
            const int col = (int)colB0 + wn * 32 + ni * 8 + 2 * t;
            const float b0 = bias[col] * bscale, b1 = bias[col + 1] * bscale;
            const float v00 = acc[mi][ni][0] + b0, v01 = acc[mi][ni][1] + b1;
            const float v10 = acc[mi][ni][2] + b0, v11 = acc[mi][ni][3] + b1;
            if (mode == 0) {
                *(float2*)&Cf[(long)row * 1024 + col] = make_float2(v00, v01);
                *(float2*)&Cf[(long)(row + 8) * 1024 + col] = make_float2(v10, v11);
            } else if (mode == 1 || mode == 3) {
                const int h = col >> 6, d = col & 63;
                const int d0 = qkmap(d), d1 = qkmap(d + 1);
#pragma unroll
                for (int half = 0; half < 2; half++) {
                    const int r2 = row + half * 8;
                    const int b_ = r2 >> 11;
                    int l = r2 & 2047;
                    if (mode == 3) l = (l & ~7) | (((l & 3) << 1) | ((l & 7) >> 2));
                    long base = ((long)(b_ * 16 + h) * 2048 + l) * 64;
                    Cu[base + d0] = f2tf(half ? v10 : v00);
                    Cu[base + d1] = f2tf(half ? v11 : v01);
                }
            } else {
                const int h = col >> 6, d = col & 63;
#pragma unroll
                for (int half = 0; half < 2; half++) {
                    const int r2 = row + half * 8;
                    const int b_ = r2 >> 11, l = r2 & 2047;
                    const int kt = l >> 6, rr = l & 63;
                    const int cst = (rr & ~7) | (((rr & 3) << 1) | ((rr & 7) >> 2));
                    long base = (long)(b_ * 16 + h) * 131072 + kt * 4096 + wvmap(cst);
                    Cu[base + d * 64]       = f2tf(half ? v10 : v00);
                    Cu[base + (d + 1) * 64] = f2tf(half ? v11 : v01);
                }
            }
        }
    }
}

// ---------------- fused QKV projection: one launch, grid (24, 64) ----------------
struct QKVParams {
    const unsigned *Aq, *Av, *Wq, *Wk, *Wv;
    const float *bq, *bk, *bv;
    unsigned *Q, *K, *V;
    float qscale;
};

__global__ __launch_bounds__(256, 2)
void gemm_qkv(QKVParams p)
{
    extern __shared__ unsigned smw[];
    const int seg = blockIdx.x >> 3;     // 0=Q, 1=K, 2=V (block-uniform)
    const int nt  = blockIdx.x & 7;
    const unsigned* A = seg == 0 ? p.Aq : p.Av;
    const unsigned* W = seg == 0 ? p.Wq : seg == 1 ? p.Wk : p.Wv;
    const float* bias = seg == 0 ? p.bq : seg == 1 ? p.bk : p.bv;
    unsigned* C       = seg == 0 ? p.Q  : seg == 1 ? p.K  : p.V;
    const float bscale = seg == 0 ? p.qscale : 1.0f;
    const int mode = seg == 0 ? 1 : seg == 1 ? 3 : 2;
    gemm_body(A, W, bias, bscale, C, mode, nt, blockIdx.y, smw);
}

// ---------------- plain GEMM (output projection) ----------------
__global__ __launch_bounds__(256, 2)
void gemm_tf32(const unsigned* __restrict__ A, const unsigned* __restrict__ W,
               const float* __restrict__ bias, float bscale, void* Cv, int mode)
{
    extern __shared__ unsigned smw[];
    gemm_body(A, W, bias, bscale, Cv, mode, blockIdx.x, blockIdx.y, smw);
}

// ---------------- tf32 flash attention (unchanged, passing) ----------------
#define ATT_SMEM (24576 * 4)   // 98304B

__global__ __launch_bounds__(256, 2)
void attn_tf32(const unsigned* __restrict__ Q, const unsigned* __restrict__ K,
               const unsigned* __restrict__ V, unsigned* __restrict__ ctx)
{
    extern __shared__ unsigned smw[];
    unsigned* Kb0 = smw;
    unsigned* Kb1 = smw + 4096;
    unsigned* Vb0 = smw + 8192;
    unsigned* Vb1 = smw + 12288;
    unsigned* Qs  = smw + 16384;

    const int tid  = threadIdx.x;
    const int lane = tid & 31;
    const int warp = tid >> 5;
    const int g = lane >> 2, t = lane & 3;
    const int qt = blockIdx.x, h = blockIdx.y, b = blockIdx.z;
    const long base = (long)(b * 16 + h) * 131072;
    const int qr = warp * 16;
    const int swz = (g & 1) << 4;

    auto issueKV = [&](unsigned* Kd, unsigned* Vd, int kt) {
        const unsigned* ksrc = K + base + kt * 4096;
        const unsigned* vsrc = V + base + kt * 4096;
#pragma unroll
        for (int i = 0; i < 4; i++) {
            const int idx = tid + i * 256;
            const int r = idx >> 4, cp = idx & 15;
            const int w = r * 64 + ((cp * 4) ^ ((r & 1) << 4));
            CP16(smem_u32(Kd + w), ksrc + r * 64 + cp * 4);
            CP16(smem_u32(Vd + w), vsrc + r * 64 + cp * 4);
        }
        CP_COMMIT();
    };

    {
        const unsigned* qsrc = Q + base + (long)qt * 8192;
#pragma unroll
        for (int i = 0; i < 8; i++) {
            const int idx = tid + i * 256;
            const int r = idx >> 4, cp = idx & 15;
            CP16(smem_u32(Qs + r * 64 + ((cp * 4) ^ ((r & 1) << 4))), qsrc + r * 64 + cp * 4);
        }
        CP_COMMIT();
    }
    issueKV(Kb0, Vb0, 0);
    CP_WAIT(1);
    __syncthreads();

    unsigned qf[8][4];
#pragma unroll
    for (int m = 0; m < 4; m++) {
        const int co = (m * 16 + t * 4) ^ swz;
        uint4 u = *(const uint4*)(Qs + (qr + g) * 64 + co);
        uint4 v = *(const uint4*)(Qs + (qr + g + 8) * 64 + co);
        qf[2 * m][0]     = u.x; qf[2 * m][1]     = v.x; qf[2 * m][2]     = u.y; qf[2 * m][3]     = v.y;
        qf[2 * m + 1][0] = u.z; qf[2 * m + 1][1] = v.z; qf[2 * m + 1][2] = u.w; qf[2 * m + 1][3] = v.w;
    }

    float l0 = 0.f, l1 = 0.f;
    float o[8][4];
#pragma unroll
    for (int ni = 0; ni < 8; ni++)
#pragma unroll
        for (int r = 0; r < 4; r++) o[ni][r] = 0.f;

    for (int kt = 0; kt < 32; kt++) {
        CP_WAIT(0);
        __syncthreads();
        if (kt < 31) issueKV((kt & 1) ? Kb0 : Kb1, (kt & 1) ? Vb0 : Vb1, kt + 1);
        const unsigned* Kw = (kt & 1) ? Kb1 : Kb0;
        const unsigned* Vw = (kt & 1) ? Vb1 : Vb0;

        float s[8][4];
#pragma unroll
        for (int ni = 0; ni < 8; ni++) {
#pragma unroll
            for (int r = 0; r < 4; r++) s[ni][r] = 0.f;
            const int rk = (ni * 8 + g) * 64;
#pragma unroll
            for (int m = 0; m < 4; m++) {
                uint4 kb = *(const uint4*)(Kw + rk + ((m * 16 + t * 4) ^ swz));
                unsigned bfA[2] = { kb.x, kb.y };
                unsigned bfB[2] = { kb.z, kb.w };
                mma8(s[ni], qf[2 * m], bfA);
                mma8(s[ni], qf[2 * m + 1], bfB);
            }
        }

#pragma unroll
        for (int ni = 0; ni < 8; ni++) {
            s[ni][0] = __uint_as_float(f2tf(ex2(s[ni][0]))); l0 += s[ni][0];
            s[ni][1] = __uint_as_float(f2tf(ex2(s[ni][1]))); l0 += s[ni][1];
            s[ni][2] = __uint_as_float(f2tf(ex2(s[ni][2]))); l1 += s[ni][2];
            s[ni][3] = __uint_as_float(f2tf(ex2(s[ni][3]))); l1 += s[ni][3];
        }

#pragma unroll
        for (int ni = 0; ni < 8; ni++) {
            const int rd = (ni * 8 + g) * 64;
#pragma unroll
            for (int m = 0; m < 4; m++) {
                uint4 vb = *(const uint4*)(Vw + rd + ((m * 16 + t * 4) ^ swz));
                unsigned pfA[4] = { __float_as_uint(s[2 * m][0]), __float_as_uint(s[2 * m][2]),
                                    __float_as_uint(s[2 * m][1]), __float_as_uint(s[2 * m][3]) };
                unsigned pfB[4] = { __float_as_uint(s[2 * m + 1][0]), __float_as_uint(s[2 * m + 1][2]),
                                    __float_as_uint(s[2 * m + 1][1]), __float_as_uint(s[2 * m + 1][3]) };
                unsigned bfA[2] = { vb.x, vb.y };
                unsigned bfB[2] = { vb.z, vb.w };
                mma8(o[ni], pfA, bfA);
                mma8(o[ni], pfB, bfB);
            }
        }
    }

    l0 += __shfl_xor_sync(0xffffffffu, l0, 1);
    l0 += __shfl_xor_sync(0xffffffffu, l0, 2);
    l1 += __shfl_xor_sync(0xffffffffu, l1, 1);
    l1 += __shfl_xor_sync(0xffffffffu, l1, 2);
    const float inv0 = 1.0f / l0, inv1 = 1.0f / l1;
    const int row0 = qt * 128 + qr + g;
#pragma unroll
    for (int ni = 0; ni < 8; ni++) {
        const int c = h * 64 + ni * 8 + 2 * t;
        const int cm0 = gmap(c), cm1 = gmap(c + 1);
        long p0 = ((long)(b * 2048 + row0)) * 1024;
        long p1 = ((long)(b * 2048 + row0 + 8)) * 1024;
        ctx[p0 + cm0] = f2tf(o[ni][0] * inv0);
        ctx[p0 + cm1] = f2tf(o[ni][1] * inv0);
        ctx[p1 + cm0] = f2tf(o[ni][2] * inv1);
        ctx[p1 + cm1] = f2tf(o[ni][3] * inv1);
    }
}

// ---------------- launch ----------------
extern "C" void kernel_launch(void* const* d_in, const int* in_sizes, int n_in,
                              void* d_out, int out_size)
{
    const float* query = (const float*)d_in[0];
    const float* value = (const float*)d_in[1];
    const float* wq = (const float*)d_in[2];
    const float* bq = (const float*)d_in[3];
    const float* wk = (const float*)d_in[4];
    const float* bk = (const float*)d_in[5];
    const float* wv = (const float*)d_in[6];
    const float* bv = (const float*)d_in[7];
    const float* wo = (const float*)d_in[8];
    const float* bo = (const float*)d_in[9];
    float* out = (float*)d_out;

    unsigned *Aq, *Av, *Wq, *Wk, *Wv, *Wo, *Qp, *Kp, *Vp, *Cp;
    cudaGetSymbolAddress((void**)&Aq, g_Aq);
    cudaGetSymbolAddress((void**)&Av, g_Av);
    cudaGetSymbolAddress((void**)&Wq, g_Wq);
    cudaGetSymbolAddress((void**)&Wk, g_Wk);
    cudaGetSymbolAddress((void**)&Wv, g_Wv);
    cudaGetSymbolAddress((void**)&Wo, g_Wo);
    cudaGetSymbolAddress((void**)&Qp, g_Q);
    cudaGetSymbolAddress((void**)&Kp, g_K);
    cudaGetSymbolAddress((void**)&Vp, g_V);
    cudaGetSymbolAddress((void**)&Cp, g_ctx);

    const float qscale = 0.125f * LOG2E;
    const int nA = M_TOTAL * D_MODEL;
    const int nW = D_MODEL * D_MODEL;

    cvt_inputs<<<2 * nA / 256, 256>>>(query, value, Aq, Av);
    cvt_weights<<<4 * nW / 256, 256>>>(wq, wk, wv, wo, Wq, Wk, Wv, Wo, qscale);

    cudaFuncSetAttribute(gemm_qkv,  cudaFuncAttributeMaxDynamicSharedMemorySize, GEMM_SMEM);
    cudaFuncSetAttribute(gemm_tf32, cudaFuncAttributeMaxDynamicSharedMemorySize, GEMM_SMEM);
    cudaFuncSetAttribute(attn_tf32, cudaFuncAttributeMaxDynamicSharedMemorySize, ATT_SMEM);

    QKVParams p;
    p.Aq = Aq; p.Av = Av; p.Wq = Wq; p.Wk = Wk; p.Wv = Wv;
    p.bq = bq; p.bk = bk; p.bv = bv;
    p.Q = Qp; p.K = Kp; p.V = Vp;
    p.qscale = qscale;

    gemm_qkv<<<dim3(24, 64), 256, GEMM_SMEM>>>(p);

    attn_tf32<<<dim3(16, 16, 4), 256, ATT_SMEM>>>(Qp, Kp, Vp, Cp);

    gemm_tf32<<<dim3(8, 64), 256, GEMM_SMEM>>>(Cp, Wo, bo, 1.0f, out, 0);
    (void)in_sizes; (void)n_in; (void)out_size;
}